// round 14
// baseline (speedup 1.0000x reference)
#include <cuda_runtime.h>

#define BB 16
#define NN 512
#define DD 256
#define HH 8
#define DKK 32

// Scratch (device globals). g_Q/g_K/g_V/g_X hold tf32-rounded bit patterns.
__device__ __align__(128) float g_Q[BB * NN * DD];
__device__ __align__(128) float g_K[BB * NN * DD];
__device__ __align__(128) float g_V[BB * NN * DD];
__device__ __align__(128) float g_X[BB * NN * DD];
__device__ __align__(128) float g_G[BB * NN * NN];
__device__ int g_cnt[BB];   // per-batch arrival counters (zeroed each launch)

// ---------------------------------------------------------------------------
// helpers
// ---------------------------------------------------------------------------
__device__ __forceinline__ unsigned f2tf(float x) {
    unsigned r;
    asm("cvt.rna.tf32.f32 %0, %1;" : "=r"(r) : "f"(x));
    return r;
}

__device__ __forceinline__ float ex2(float x) {
    float y;
    asm("ex2.approx.ftz.f32 %0, %1;" : "=f"(y) : "f"(x));
    return y;
}

__device__ __forceinline__ void mma8(float* c,
                                     unsigned a0, unsigned a1, unsigned a2, unsigned a3,
                                     unsigned b0, unsigned b1) {
    asm volatile(
        "mma.sync.aligned.m16n8k8.row.col.f32.tf32.tf32.f32 "
        "{%0,%1,%2,%3},{%4,%5,%6,%7},{%8,%9},{%0,%1,%2,%3};"
        : "+f"(c[0]), "+f"(c[1]), "+f"(c[2]), "+f"(c[3])
        : "r"(a0), "r"(a1), "r"(a2), "r"(a3), "r"(b0), "r"(b1));
}

__device__ __forceinline__ void cpa16(unsigned saddr, const void* gptr) {
    asm volatile("cp.async.cg.shared.global [%0], [%1], 16;" :: "r"(saddr), "l"(gptr));
}
#define CP_COMMIT() asm volatile("cp.async.commit_group;")
#define CP_WAIT0()  asm volatile("cp.async.wait_group 0;")

// ---------------------------------------------------------------------------
// GEMM core v4b (identical to R13): Y = X @ W^T + bias; K=256. 256 thr.
// ---------------------------------------------------------------------------
#define GS_X 4608
#define GS_W 2304
#define GEMM_SMEM_BYTES ((2 * GS_X + 2 * GS_W) * 4)

__device__ __forceinline__ void gemm_issue4(
    unsigned sb, const float* __restrict__ X, const float* __restrict__ W,
    int m0, int n0, int kt, int tid)
{
    int buf = kt & 1;
#pragma unroll
    for (int i = 0; i < 4; i++) {
        int e = tid + 256 * i, r = e >> 3, c = e & 7;
        cpa16(sb + 4 * (buf * GS_X + r * 36 + 4 * c),
              &X[(size_t)(m0 + r) * DD + kt * 32 + 4 * c]);
    }
#pragma unroll
    for (int i = 0; i < 2; i++) {
        int e = tid + 256 * i, r = e >> 3, c = e & 7;
        cpa16(sb + 4 * (2 * GS_X + buf * GS_W + r * 36 + 4 * c),
              &W[(size_t)(n0 + r) * DD + kt * 32 + 4 * c]);
    }
    CP_COMMIT();
}

__device__ __forceinline__ void gemm_core4(
    const float* __restrict__ X, const float* __restrict__ W,
    const float* __restrict__ bias, float* __restrict__ Y,
    int cvt_a, int cvt_out, float* sm, int m0, int n0)
{
    const int tid = threadIdx.x;
    const int warp = tid >> 5, lane = tid & 31;
    const int g = lane >> 2, tig = lane & 3;
    const int wm = warp >> 1, wn = warp & 1;
    unsigned sb = (unsigned)__cvta_generic_to_shared(sm);

    float acc[2][4][4];
#pragma unroll
    for (int mt = 0; mt < 2; mt++)
#pragma unroll
        for (int nt = 0; nt < 4; nt++)
#pragma unroll
            for (int i = 0; i < 4; i++) acc[mt][nt][i] = 0.f;

    gemm_issue4(sb, X, W, m0, n0, 0, tid);

    for (int kt = 0; kt < 8; kt++) {
        CP_WAIT0();
        __syncthreads();
        if (kt < 7) gemm_issue4(sb, X, W, m0, n0, kt + 1, tid);

        const float* xb = sm + (kt & 1) * GS_X;
        const float* wb = sm + 2 * GS_X + (kt & 1) * GS_W;
        const unsigned* xbu = (const unsigned*)xb;

#pragma unroll
        for (int k8 = 0; k8 < 4; k8++) {
            int k0 = k8 * 8;
            unsigned a[2][4];
#pragma unroll
            for (int mt = 0; mt < 2; mt++) {
                int r = wm * 32 + mt * 16;
                if (cvt_a) {
                    a[mt][0] = f2tf(xb[(r + g) * 36 + k0 + tig]);
                    a[mt][1] = f2tf(xb[(r + g + 8) * 36 + k0 + tig]);
                    a[mt][2] = f2tf(xb[(r + g) * 36 + k0 + tig + 4]);
                    a[mt][3] = f2tf(xb[(r + g + 8) * 36 + k0 + tig + 4]);
                } else {
                    a[mt][0] = xbu[(r + g) * 36 + k0 + tig];
                    a[mt][1] = xbu[(r + g + 8) * 36 + k0 + tig];
                    a[mt][2] = xbu[(r + g) * 36 + k0 + tig + 4];
                    a[mt][3] = xbu[(r + g + 8) * 36 + k0 + tig + 4];
                }
            }
#pragma unroll
            for (int nt = 0; nt < 4; nt++) {
                int cb = wn * 32 + nt * 8;
                unsigned b0 = f2tf(wb[(cb + g) * 36 + k0 + tig]);
                unsigned b1 = f2tf(wb[(cb + g) * 36 + k0 + tig + 4]);
                mma8(acc[0][nt], a[0][0], a[0][1], a[0][2], a[0][3], b0, b1);
                mma8(acc[1][nt], a[1][0], a[1][1], a[1][2], a[1][3], b0, b1);
            }
        }
    }

#pragma unroll
    for (int mt = 0; mt < 2; mt++) {
        int row = m0 + wm * 32 + mt * 16 + g;
#pragma unroll
        for (int nt = 0; nt < 4; nt++) {
            int col = n0 + wn * 32 + nt * 8 + 2 * tig;
            float b0 = bias[col], b1 = bias[col + 1];
            float v00 = acc[mt][nt][0] + b0, v01 = acc[mt][nt][1] + b1;
            float v10 = acc[mt][nt][2] + b0, v11 = acc[mt][nt][3] + b1;
            if (cvt_out) {
                v00 = __uint_as_float(f2tf(v00)); v01 = __uint_as_float(f2tf(v01));
                v10 = __uint_as_float(f2tf(v10)); v11 = __uint_as_float(f2tf(v11));
            }
            *(float2*)&Y[(size_t)row * DD + col] = make_float2(v00, v01);
            *(float2*)&Y[(size_t)(row + 8) * DD + col] = make_float2(v10, v11);
        }
    }
}

// ---------------------------------------------------------------------------
// Fused launch 1 (identical to R13): z=0/1/2 -> Q/K/V projection;
// z=3 -> build_G (warp-per-row, no barriers) + counter zeroing.
// ---------------------------------------------------------------------------
__global__ void __launch_bounds__(256, 4) fused_qkv_g(
    const float* __restrict__ query, const float* __restrict__ key_,
    const float* __restrict__ value,
    const float* __restrict__ Wq, const float* __restrict__ bq,
    const float* __restrict__ Wk, const float* __restrict__ bk,
    const float* __restrict__ Wv, const float* __restrict__ bv,
    const float* __restrict__ dist, const float* __restrict__ adj,
    const int* __restrict__ mask)
{
    extern __shared__ float sm[];
    const int z = blockIdx.z;
    if (z < 3) {
        const float* X = (z == 0) ? query : (z == 1) ? key_ : value;
        const float* W = (z == 0) ? Wq : (z == 1) ? Wk : Wv;
        const float* bias = (z == 0) ? bq : (z == 1) ? bk : bv;
        float* Y = (z == 0) ? g_Q : (z == 1) ? g_K : g_V;
        gemm_core4(X, W, bias, Y, 1, 1, sm, blockIdx.x * 128, blockIdx.y * 64);
        return;
    }

    const int id = blockIdx.y * 64 + blockIdx.x;   // 0..255
    if (id == 0 && threadIdx.x < BB) g_cnt[threadIdx.x] = 0;

    const int bb = id >> 4;
    const int r0 = (id & 15) * 32;
    const int warp = threadIdx.x >> 5, lane = threadIdx.x & 31;

    float v[16];
#pragma unroll
    for (int i = 0; i < 4; i++) {
        int4 mv = *(const int4*)&mask[bb * NN + 4 * lane + 128 * i];
        v[4 * i + 0] = mv.x ? 1.f : 0.f;
        v[4 * i + 1] = mv.y ? 1.f : 0.f;
        v[4 * i + 2] = mv.z ? 1.f : 0.f;
        v[4 * i + 3] = mv.w ? 1.f : 0.f;
    }

    for (int rr = 0; rr < 4; rr++) {
        int row = r0 + warp * 4 + rr;
        size_t rb = ((size_t)bb * NN + row) * NN;

        float4 d4[4], a4[4];
#pragma unroll
        for (int i = 0; i < 4; i++) {
            d4[i] = *(const float4*)&dist[rb + 4 * lane + 128 * i];
            a4[i] = *(const float4*)&adj[rb + 4 * lane + 128 * i];
        }
        float e[16];
        float se = 0.f, sa = 0.f;
#pragma unroll
        for (int i = 0; i < 4; i++) {
            e[4 * i + 0] = v[4 * i + 0] * __expf(-d4[i].x);
            e[4 * i + 1] = v[4 * i + 1] * __expf(-d4[i].y);
            e[4 * i + 2] = v[4 * i + 2] * __expf(-d4[i].z);
            e[4 * i + 3] = v[4 * i + 3] * __expf(-d4[i].w);
            se += (e[4 * i] + e[4 * i + 1]) + (e[4 * i + 2] + e[4 * i + 3]);
            sa += (a4[i].x + a4[i].y) + (a4[i].z + a4[i].w);
        }
#pragma unroll
        for (int o = 16; o > 0; o >>= 1) {
            se += __shfl_xor_sync(0xffffffffu, se, o);
            sa += __shfl_xor_sync(0xffffffffu, sa, o);
        }
        float invd = 0.3f / se;
        float inva = 0.4f / (sa + 1e-6f);
#pragma unroll
        for (int i = 0; i < 4; i++) {
            *(float4*)&g_G[rb + 4 * lane + 128 * i] = make_float4(
                e[4 * i + 0] * invd + a4[i].x * inva,
                e[4 * i + 1] * invd + a4[i].y * inva,
                e[4 * i + 2] * invd + a4[i].z * inva,
                e[4 * i + 3] * invd + a4[i].w * inva);
        }
    }
}

// ---------------------------------------------------------------------------
// Persistent attention v5 + fused output projection tail.
// V stored at stride 40 (conflict-free B-fragment loads). Q fragments live in
// registers, prefetched one tile ahead via LDG. G staged per tile (stride 520,
// conflict-free blend reads), aliasing the Ored exchange buffer.
// ---------------------------------------------------------------------------
#define SM_K   0
#define SM_V   (512 * 36)                   // K: 512 x 36
#define SM_PS  (SM_V + 512 * 40)            // V: 512 x 40 (conflict-free)
#define SM_GO  (SM_PS + 256)                // G stage (32 x 520) / Ored alias
#define GST    520
#define ORS    34
#define ATT_SMEM ((SM_GO + 32 * GST) * 4)   // 223232 B

__global__ void __launch_bounds__(512) attn_tc(
    const int* __restrict__ mask,
    const float* __restrict__ Wo, const float* __restrict__ bo,
    float* __restrict__ out)
{
    extern __shared__ unsigned smu[];
    const unsigned* Ks = smu + SM_K;
    const unsigned* Vs = smu + SM_V;
    float* psum = (float*)(smu + SM_PS);
    float* Gs = (float*)(smu + SM_GO);
    float* Ored = (float*)(smu + SM_GO);    // alias (disjoint in time)

    const int h = blockIdx.x, b = blockIdx.y;
    const int tid = threadIdx.x, warp = tid >> 5, lane = tid & 31;
    const int g = lane >> 2, tig = lane & 3;
    unsigned sb = (unsigned)__cvta_generic_to_shared(smu);

    const int wm = warp >> 3, wn = warp & 7;
    const unsigned* gQu = (const unsigned*)g_Q;

    // One-time cp.async: K (stride 36), V (stride 40), G tile 0 (stride 520)
#pragma unroll
    for (int i = 0; i < 8; i++) {
        int e = tid + 512 * i, r = e >> 3, c = e & 7;
        cpa16(sb + 4 * (SM_K + r * 36 + 4 * c),
              &g_K[((size_t)(b * NN + r)) * DD + h * DKK + 4 * c]);
        cpa16(sb + 4 * (SM_V + r * 40 + 4 * c),
              &g_V[((size_t)(b * NN + r)) * DD + h * DKK + 4 * c]);
    }
#pragma unroll
    for (int i = 0; i < 8; i++) {
        int e = tid + 512 * i, r = e >> 7, c4 = (e & 127) * 4;
        cpa16(sb + 4 * (SM_GO + r * GST + c4),
              &g_G[((size_t)(b * NN + r)) * NN + c4]);
    }
    CP_COMMIT();

    // Q fragments for tile 0 -> registers (LDG)
    unsigned qa[4][4];
    {
        size_t base0 = ((size_t)(b * NN + wm * 16 + g)) * DD + h * DKK;
        size_t base8 = base0 + 8 * DD;
#pragma unroll
        for (int k8 = 0; k8 < 4; k8++) {
            int k0 = k8 * 8;
            qa[k8][0] = gQu[base0 + k0 + tig];
            qa[k8][1] = gQu[base8 + k0 + tig];
            qa[k8][2] = gQu[base0 + k0 + tig + 4];
            qa[k8][3] = gQu[base8 + k0 + tig + 4];
        }
    }

    // validity mask -> registers (tile-invariant per warp/lane)
    float v0[8], v1[8];
#pragma unroll
    for (int nt = 0; nt < 8; nt++) {
        int c = wn * 64 + nt * 8 + 2 * tig;
        v0[nt] = (mask[b * NN + c] != 0) ? 1.f : 0.f;
        v1[nt] = (mask[b * NN + c + 1] != 0) ? 1.f : 0.f;
    }
    CP_WAIT0();
    __syncthreads();

    const float EC = 0.17677669529663687f * 1.4426950408889634f;
    const int src0 = (lane & ~3) | (tig >> 1);
    const int src2 = (lane & ~3) | ((tig >> 1) + 2);
    const bool odd = (tig & 1) != 0;

    for (int qt = 0; qt < 16; qt++) {
        const int q0 = qt * 32;

        // --- P1: S = Q(regs) K^T; scores in registers
        float acc[8][4];
        {
#pragma unroll
            for (int nt = 0; nt < 8; nt++)
#pragma unroll
                for (int i = 0; i < 4; i++) acc[nt][i] = 0.f;
#pragma unroll
            for (int k8 = 0; k8 < 4; k8++) {
                int k0 = k8 * 8;
#pragma unroll
                for (int nt = 0; nt < 8; nt++) {
                    int key = wn * 64 + nt * 8;
                    unsigned b0 = Ks[(key + g) * 36 + k0 + tig];
                    unsigned b1 = Ks[(key + g) * 36 + k0 + tig + 4];
                    mma8(acc[nt], qa[k8][0], qa[k8][1], qa[k8][2], qa[k8][3], b0, b1);
                }
            }
        }

        // Prefetch Q fragments for tile qt+1 (registers; full-tile latency hide)
        unsigned qn[4][4];
        if (qt < 15) {
            size_t base0 = ((size_t)(b * NN + q0 + 32 + wm * 16 + g)) * DD + h * DKK;
            size_t base8 = base0 + 8 * DD;
#pragma unroll
            for (int k8 = 0; k8 < 4; k8++) {
                int k0 = k8 * 8;
                qn[k8][0] = gQu[base0 + k0 + tig];
                qn[k8][1] = gQu[base8 + k0 + tig];
                qn[k8][2] = gQu[base0 + k0 + tig + 4];
                qn[k8][3] = gQu[base8 + k0 + tig + 4];
            }
        }

        // exp * validity (regs); partial row sums -> psum
        float s0 = 0.f, s8 = 0.f;
#pragma unroll
        for (int nt = 0; nt < 8; nt++) {
            acc[nt][0] = ex2(acc[nt][0] * EC) * v0[nt];
            acc[nt][1] = ex2(acc[nt][1] * EC) * v1[nt];
            acc[nt][2] = ex2(acc[nt][2] * EC) * v0[nt];
            acc[nt][3] = ex2(acc[nt][3] * EC) * v1[nt];
            s0 += acc[nt][0] + acc[nt][1];
            s8 += acc[nt][2] + acc[nt][3];
        }
        s0 += __shfl_xor_sync(0xffffffffu, s0, 1);
        s0 += __shfl_xor_sync(0xffffffffu, s0, 2);
        s8 += __shfl_xor_sync(0xffffffffu, s8, 1);
        s8 += __shfl_xor_sync(0xffffffffu, s8, 2);
        if (tig == 0) {
            psum[(wm * 16 + g) * 8 + wn] = s0;
            psum[(wm * 16 + g + 8) * 8 + wn] = s8;
        }

        CP_WAIT0();        // G(qt) landed (only group in flight)
        __syncthreads();   // (1) psum + Gs(qt) visible

        // psum reduce + blend with Gs (conflict-free float2 LDS)
        {
            int r0 = wm * 16 + g, r8 = r0 + 8;
            float t0 = 0.f, t8 = 0.f;
#pragma unroll
            for (int i = 0; i < 8; i++) { t0 += psum[r0 * 8 + i]; t8 += psum[r8 * 8 + i]; }
            float inv0 = 0.3f / t0, inv8 = 0.3f / t8;
            const float* G0 = Gs + r0 * GST;
            const float* G8 = Gs + r8 * GST;
#pragma unroll
            for (int nt = 0; nt < 8; nt++) {
                int c = wn * 64 + nt * 8 + 2 * tig;
                float2 gv0 = *(const float2*)&G0[c];
                float2 gv8 = *(const float2*)&G8[c];
                acc[nt][0] = fmaf(acc[nt][0], inv0, gv0.x);
                acc[nt][1] = fmaf(acc[nt][1], inv0, gv0.y);
                acc[nt][2] = fmaf(acc[nt][2], inv8, gv8.x);
                acc[nt][3] = fmaf(acc[nt][3], inv8, gv8.y);
            }
        }
        __syncthreads();   // (B) all Gs reads done before Ored writes (alias)

        // --- P2: C->A shfl conversion, partial O over this warp's 64 keys
        {
            float accO[4][4];
#pragma unroll
            for (int nt2 = 0; nt2 < 4; nt2++)
#pragma unroll
                for (int i = 0; i < 4; i++) accO[nt2][i] = 0.f;

#pragma unroll
            for (int nt = 0; nt < 8; nt++) {
                float t00 = __shfl_sync(0xffffffffu, acc[nt][0], src0);
                float t01 = __shfl_sync(0xffffffffu, acc[nt][1], src0);
                float t20 = __shfl_sync(0xffffffffu, acc[nt][0], src2);
                float t21 = __shfl_sync(0xffffffffu, acc[nt][1], src2);
                float t10 = __shfl_sync(0xffffffffu, acc[nt][2], src0);
                float t11 = __shfl_sync(0xffffffffu, acc[nt][3], src0);
                float t30 = __shfl_sync(0xffffffffu, acc[nt][2], src2);
                float t31 = __shfl_sync(0xffffffffu, acc[nt][3], src2);
                unsigned a0 = f2tf(odd ? t01 : t00);
                unsigned a1 = f2tf(odd ? t11 : t10);
                unsigned a2 = f2tf(odd ? t21 : t20);
                unsigned a3 = f2tf(odd ? t31 : t30);
                int kv0 = wn * 64 + nt * 8;
#pragma unroll
                for (int nt2 = 0; nt2 < 4; nt2++) {
                    unsigned b0 = Vs[(kv0 + tig) * 40 + nt2 * 8 + g];
                    unsigned b1 = Vs[(kv0 + tig + 4) * 40 + nt2 * 8 + g];
                    mma8(accO[nt2], a0, a1, a2, a3, b0, b1);
                }
            }

            float* Or = Ored + wn * (32 * ORS);
            int r0 = wm * 16 + g;
#pragma unroll
            for (int nt2 = 0; nt2 < 4; nt2++) {
                int c = nt2 * 8 + 2 * tig;
                *(float2*)&Or[r0 * ORS + c] = make_float2(accO[nt2][0], accO[nt2][1]);
                *(float2*)&Or[(r0 + 8) * ORS + c] = make_float2(accO[nt2][2], accO[nt2][3]);
            }
        }
        __syncthreads();   // (2) Ored published

        // reduce 8 partials -> g_X (tf32 bits)
        {
            int row = tid >> 4, c2 = (tid & 15) << 1;
            float sx = 0.f, sy = 0.f;
#pragma unroll
            for (int w2 = 0; w2 < 8; w2++) {
                float2 v = *(const float2*)&Ored[w2 * (32 * ORS) + row * ORS + c2];
                sx += v.x; sy += v.y;
            }
            int grow = b * NN + q0 + row;
            int gcol = h * DKK + c2;
            *(float2*)&g_X[(size_t)grow * DD + gcol] =
                make_float2(__uint_as_float(f2tf(sx)), __uint_as_float(f2tf(sy)));
        }
        __syncthreads();   // (3) Ored reads done before next G fill overwrites

        // Issue G fill for next tile (overlaps next P1/exp)
        if (qt < 15) {
#pragma unroll
            for (int i = 0; i < 8; i++) {
                int e = tid + 512 * i, r = e >> 7, c4 = (e & 127) * 4;
                cpa16(sb + 4 * (SM_GO + r * GST + c4),
                      &g_G[((size_t)(b * NN + q0 + 32 + r)) * NN + c4]);
            }
            CP_COMMIT();
            // rotate Q fragment registers
#pragma unroll
            for (int k8 = 0; k8 < 4; k8++)
#pragma unroll
                for (int i = 0; i < 4; i++) qa[k8][i] = qn[k8][i];
        }
    }

    // ====================== fused output-projection tail ======================
    __threadfence();
    __syncthreads();
    if (tid == 0) {
        atomicAdd(&g_cnt[b], 1);
        while (atomicAdd(&g_cnt[b], 0) < HH) { }
    }
    __syncthreads();
    __threadfence();

    {
        const int m0 = b * NN + (h >> 1) * 128;
        const int n0 = (h & 1) * 128;
        const int twm = warp >> 2, twn = warp & 3;
        float* Xb = (float*)smu;             // K region
        float* Wb = (float*)(smu + SM_V);    // V region

#define TAIL_ISSUE(kt, buf)                                                    \
        do {                                                                   \
            _Pragma("unroll")                                                  \
            for (int i = 0; i < 2; i++) {                                      \
                int e = tid + 512 * i, r = e >> 3, c = e & 7;                  \
                cpa16(sb + 4 * ((buf) * 4608 + r * 36 + 4 * c),                \
                      &g_X[(size_t)(m0 + r) * DD + (kt) * 32 + 4 * c]);        \
                cpa16(sb + 4 * (SM_V + (buf) * 4608 + r * 36 + 4 * c),         \
                      &Wo[(size_t)(n0 + r) * DD + (kt) * 32 + 4 * c]);         \
            }                                                                  \
            CP_COMMIT();                                                       \
        } while (0)

        float acc[2][4][4];
#pragma unroll
        for (int mt = 0; mt < 2; mt++)
#pragma unroll
            for (int nt = 0; nt < 4; nt++)
#pragma unroll
                for (int i = 0; i < 4; i++) acc[mt][nt][i] = 0.f;

        TAIL_ISSUE(0, 0);
        for (int kt = 0; kt < 8; kt++) {
            CP_WAIT0();
            __syncthreads();
            if (kt < 7) TAIL_ISSUE(kt + 1, (kt + 1) & 1);

            const unsigned* xb = (const unsigned*)(Xb + (kt & 1) * 4608);
            const float* wb = Wb + (kt & 1) * 4608;

#pragma unroll
            for (int k8 = 0; k8 < 4; k8++) {
                int k0 = k8 * 8;
                unsigned a[2][4];
#pragma unroll
                for (int mt = 0; mt < 2; mt++) {
                    int r = twm * 32 + mt * 16;
                    a[mt][0] = xb[(r + g) * 36 + k0 + tig];
                    a[mt][1] = xb[(r + g + 8) * 36 + k0 + tig];
                    a[mt][2] = xb[(r + g) * 36 + k0 + tig + 4];
                    a[mt][3] = xb[(r + g + 8) * 36 + k0 + tig + 4];
                }
#pragma unroll
                for (int nt = 0; nt < 4; nt++) {
                    int cb = twn * 32 + nt * 8;
                    unsigned b0 = f2tf(wb[(cb + g) * 36 + k0 + tig]);
                    unsigned b1 = f2tf(wb[(cb + g) * 36 + k0 + tig + 4]);
                    mma8(acc[0][nt], a[0][0], a[0][1], a[0][2], a[0][3], b0, b1);
                    mma8(acc[1][nt], a[1][0], a[1][1], a[1][2], a[1][3], b0, b1);
                }
            }
        }

#pragma unroll
        for (int mt = 0; mt < 2; mt++) {
            int row = m0 + twm * 32 + mt * 16 + g;
#pragma unroll
            for (int nt = 0; nt < 4; nt++) {
                int col = n0 + twn * 32 + nt * 8 + 2 * tig;
                float b0 = bo[col], b1 = bo[col + 1];
                *(float2*)&out[(size_t)row * DD + col] =
                    make_float2(acc[mt][nt][0] + b0, acc[mt][nt][1] + b1);
                *(float2*)&out[(size_t)(row + 8) * DD + col] =
                    make_float2(acc[mt][nt][2] + b0, acc[mt][nt][3] + b1);
            }
        }
#undef TAIL_ISSUE
    }
}

// ---------------------------------------------------------------------------
// Launch: two kernels total.
// ---------------------------------------------------------------------------
extern "C" void kernel_launch(void* const* d_in, const int* in_sizes, int n_in,
                              void* d_out, int out_size)
{
    (void)in_sizes; (void)n_in; (void)out_size;
    const float* query = (const float*)d_in[0];
    const float* key_  = (const float*)d_in[1];
    const float* value = (const float*)d_in[2];
    const float* adj   = (const float*)d_in[3];
    const float* dist  = (const float*)d_in[4];
    const int*   mask  = (const int*)d_in[6];
    const float* Wq = (const float*)d_in[7],  *bq = (const float*)d_in[8];
    const float* Wk = (const float*)d_in[9],  *bk = (const float*)d_in[10];
    const float* Wv = (const float*)d_in[11], *bv = (const float*)d_in[12];
    const float* Wo = (const float*)d_in[13], *bo = (const float*)d_in[14];
    float* out = (float*)d_out;

    static int attr_done = 0;
    if (!attr_done) {
        cudaFuncSetAttribute(fused_qkv_g, cudaFuncAttributeMaxDynamicSharedMemorySize, GEMM_SMEM_BYTES);
        cudaFuncSetAttribute(attn_tc,     cudaFuncAttributeMaxDynamicSharedMemorySize, ATT_SMEM);
        attr_done = 1;
    }

    fused_qkv_g<<<dim3(BB * NN / 128, DD / 64, 4), 256, GEMM_SMEM_BYTES>>>(
        query, key_, value, Wq, bq, Wk, bk, Wv, bv, dist, adj, mask);

    attn_tc<<<dim3(HH, BB), 512, ATT_SMEM>>>(mask, Wo, bo, out);
}

// round 15
// speedup vs baseline: 1.0029x; 1.0029x over previous
#include <cuda_runtime.h>

#define BB 16
#define NN 512
#define DD 256
#define HH 8
#define DKK 32

// Scratch (device globals). g_Q/g_K/g_V/g_X hold tf32-rounded bit patterns.
__device__ __align__(128) float g_Q[BB * NN * DD];
__device__ __align__(128) float g_K[BB * NN * DD];
__device__ __align__(128) float g_V[BB * NN * DD];
__device__ __align__(128) float g_X[BB * NN * DD];
__device__ __align__(128) float g_G[BB * NN * NN];
__device__ int g_cnt[BB];   // per-batch arrival counters (zeroed each launch)

// ---------------------------------------------------------------------------
// helpers
// ---------------------------------------------------------------------------
__device__ __forceinline__ unsigned f2tf(float x) {
    unsigned r;
    asm("cvt.rna.tf32.f32 %0, %1;" : "=r"(r) : "f"(x));
    return r;
}

__device__ __forceinline__ float ex2(float x) {
    float y;
    asm("ex2.approx.ftz.f32 %0, %1;" : "=f"(y) : "f"(x));
    return y;
}

__device__ __forceinline__ void mma8(float* c,
                                     unsigned a0, unsigned a1, unsigned a2, unsigned a3,
                                     unsigned b0, unsigned b1) {
    asm volatile(
        "mma.sync.aligned.m16n8k8.row.col.f32.tf32.tf32.f32 "
        "{%0,%1,%2,%3},{%4,%5,%6,%7},{%8,%9},{%0,%1,%2,%3};"
        : "+f"(c[0]), "+f"(c[1]), "+f"(c[2]), "+f"(c[3])
        : "r"(a0), "r"(a1), "r"(a2), "r"(a3), "r"(b0), "r"(b1));
}

__device__ __forceinline__ void cpa16(unsigned saddr, const void* gptr) {
    asm volatile("cp.async.cg.shared.global [%0], [%1], 16;" :: "r"(saddr), "l"(gptr));
}
#define CP_COMMIT() asm volatile("cp.async.commit_group;")
#define CP_WAIT0()  asm volatile("cp.async.wait_group 0;")

// ---------------------------------------------------------------------------
// GEMM core v4b (identical): Y = X @ W^T + bias; K=256. 256 thr.
// ---------------------------------------------------------------------------
#define GS_X 4608
#define GS_W 2304
#define GEMM_SMEM_BYTES ((2 * GS_X + 2 * GS_W) * 4)

__device__ __forceinline__ void gemm_issue4(
    unsigned sb, const float* __restrict__ X, const float* __restrict__ W,
    int m0, int n0, int kt, int tid)
{
    int buf = kt & 1;
#pragma unroll
    for (int i = 0; i < 4; i++) {
        int e = tid + 256 * i, r = e >> 3, c = e & 7;
        cpa16(sb + 4 * (buf * GS_X + r * 36 + 4 * c),
              &X[(size_t)(m0 + r) * DD + kt * 32 + 4 * c]);
    }
#pragma unroll
    for (int i = 0; i < 2; i++) {
        int e = tid + 256 * i, r = e >> 3, c = e & 7;
        cpa16(sb + 4 * (2 * GS_X + buf * GS_W + r * 36 + 4 * c),
              &W[(size_t)(n0 + r) * DD + kt * 32 + 4 * c]);
    }
    CP_COMMIT();
}

__device__ __forceinline__ void gemm_core4(
    const float* __restrict__ X, const float* __restrict__ W,
    const float* __restrict__ bias, float* __restrict__ Y,
    int cvt_a, int cvt_out, float* sm, int m0, int n0)
{
    const int tid = threadIdx.x;
    const int warp = tid >> 5, lane = tid & 31;
    const int g = lane >> 2, tig = lane & 3;
    const int wm = warp >> 1, wn = warp & 1;
    unsigned sb = (unsigned)__cvta_generic_to_shared(sm);

    float acc[2][4][4];
#pragma unroll
    for (int mt = 0; mt < 2; mt++)
#pragma unroll
        for (int nt = 0; nt < 4; nt++)
#pragma unroll
            for (int i = 0; i < 4; i++) acc[mt][nt][i] = 0.f;

    gemm_issue4(sb, X, W, m0, n0, 0, tid);

    for (int kt = 0; kt < 8; kt++) {
        CP_WAIT0();
        __syncthreads();
        if (kt < 7) gemm_issue4(sb, X, W, m0, n0, kt + 1, tid);

        const float* xb = sm + (kt & 1) * GS_X;
        const float* wb = sm + 2 * GS_X + (kt & 1) * GS_W;
        const unsigned* xbu = (const unsigned*)xb;

#pragma unroll
        for (int k8 = 0; k8 < 4; k8++) {
            int k0 = k8 * 8;
            unsigned a[2][4];
#pragma unroll
            for (int mt = 0; mt < 2; mt++) {
                int r = wm * 32 + mt * 16;
                if (cvt_a) {
                    a[mt][0] = f2tf(xb[(r + g) * 36 + k0 + tig]);
                    a[mt][1] = f2tf(xb[(r + g + 8) * 36 + k0 + tig]);
                    a[mt][2] = f2tf(xb[(r + g) * 36 + k0 + tig + 4]);
                    a[mt][3] = f2tf(xb[(r + g + 8) * 36 + k0 + tig + 4]);
                } else {
                    a[mt][0] = xbu[(r + g) * 36 + k0 + tig];
                    a[mt][1] = xbu[(r + g + 8) * 36 + k0 + tig];
                    a[mt][2] = xbu[(r + g) * 36 + k0 + tig + 4];
                    a[mt][3] = xbu[(r + g + 8) * 36 + k0 + tig + 4];
                }
            }
#pragma unroll
            for (int nt = 0; nt < 4; nt++) {
                int cb = wn * 32 + nt * 8;
                unsigned b0 = f2tf(wb[(cb + g) * 36 + k0 + tig]);
                unsigned b1 = f2tf(wb[(cb + g) * 36 + k0 + tig + 4]);
                mma8(acc[0][nt], a[0][0], a[0][1], a[0][2], a[0][3], b0, b1);
                mma8(acc[1][nt], a[1][0], a[1][1], a[1][2], a[1][3], b0, b1);
            }
        }
    }

#pragma unroll
    for (int mt = 0; mt < 2; mt++) {
        int row = m0 + wm * 32 + mt * 16 + g;
#pragma unroll
        for (int nt = 0; nt < 4; nt++) {
            int col = n0 + wn * 32 + nt * 8 + 2 * tig;
            float b0 = bias[col], b1 = bias[col + 1];
            float v00 = acc[mt][nt][0] + b0, v01 = acc[mt][nt][1] + b1;
            float v10 = acc[mt][nt][2] + b0, v11 = acc[mt][nt][3] + b1;
            if (cvt_out) {
                v00 = __uint_as_float(f2tf(v00)); v01 = __uint_as_float(f2tf(v01));
                v10 = __uint_as_float(f2tf(v10)); v11 = __uint_as_float(f2tf(v11));
            }
            *(float2*)&Y[(size_t)row * DD + col] = make_float2(v00, v01);
            *(float2*)&Y[(size_t)(row + 8) * DD + col] = make_float2(v10, v11);
        }
    }
}

// ---------------------------------------------------------------------------
// Fused launch 1 (identical): z=0/1/2 -> Q/K/V projection;
// z=3 -> build_G (warp-per-row, no barriers) + counter zeroing.
// ---------------------------------------------------------------------------
__global__ void __launch_bounds__(256, 4) fused_qkv_g(
    const float* __restrict__ query, const float* __restrict__ key_,
    const float* __restrict__ value,
    const float* __restrict__ Wq, const float* __restrict__ bq,
    const float* __restrict__ Wk, const float* __restrict__ bk,
    const float* __restrict__ Wv, const float* __restrict__ bv,
    const float* __restrict__ dist, const float* __restrict__ adj,
    const int* __restrict__ mask)
{
    extern __shared__ float sm[];
    const int z = blockIdx.z;
    if (z < 3) {
        const float* X = (z == 0) ? query : (z == 1) ? key_ : value;
        const float* W = (z == 0) ? Wq : (z == 1) ? Wk : Wv;
        const float* bias = (z == 0) ? bq : (z == 1) ? bk : bv;
        float* Y = (z == 0) ? g_Q : (z == 1) ? g_K : g_V;
        gemm_core4(X, W, bias, Y, 1, 1, sm, blockIdx.x * 128, blockIdx.y * 64);
        return;
    }

    const int id = blockIdx.y * 64 + blockIdx.x;   // 0..255
    if (id == 0 && threadIdx.x < BB) g_cnt[threadIdx.x] = 0;

    const int bb = id >> 4;
    const int r0 = (id & 15) * 32;
    const int warp = threadIdx.x >> 5, lane = threadIdx.x & 31;

    float v[16];
#pragma unroll
    for (int i = 0; i < 4; i++) {
        int4 mv = *(const int4*)&mask[bb * NN + 4 * lane + 128 * i];
        v[4 * i + 0] = mv.x ? 1.f : 0.f;
        v[4 * i + 1] = mv.y ? 1.f : 0.f;
        v[4 * i + 2] = mv.z ? 1.f : 0.f;
        v[4 * i + 3] = mv.w ? 1.f : 0.f;
    }

    for (int rr = 0; rr < 4; rr++) {
        int row = r0 + warp * 4 + rr;
        size_t rb = ((size_t)bb * NN + row) * NN;

        float4 d4[4], a4[4];
#pragma unroll
        for (int i = 0; i < 4; i++) {
            d4[i] = *(const float4*)&dist[rb + 4 * lane + 128 * i];
            a4[i] = *(const float4*)&adj[rb + 4 * lane + 128 * i];
        }
        float e[16];
        float se = 0.f, sa = 0.f;
#pragma unroll
        for (int i = 0; i < 4; i++) {
            e[4 * i + 0] = v[4 * i + 0] * __expf(-d4[i].x);
            e[4 * i + 1] = v[4 * i + 1] * __expf(-d4[i].y);
            e[4 * i + 2] = v[4 * i + 2] * __expf(-d4[i].z);
            e[4 * i + 3] = v[4 * i + 3] * __expf(-d4[i].w);
            se += (e[4 * i] + e[4 * i + 1]) + (e[4 * i + 2] + e[4 * i + 3]);
            sa += (a4[i].x + a4[i].y) + (a4[i].z + a4[i].w);
        }
#pragma unroll
        for (int o = 16; o > 0; o >>= 1) {
            se += __shfl_xor_sync(0xffffffffu, se, o);
            sa += __shfl_xor_sync(0xffffffffu, sa, o);
        }
        float invd = 0.3f / se;
        float inva = 0.4f / (sa + 1e-6f);
#pragma unroll
        for (int i = 0; i < 4; i++) {
            *(float4*)&g_G[rb + 4 * lane + 128 * i] = make_float4(
                e[4 * i + 0] * invd + a4[i].x * inva,
                e[4 * i + 1] * invd + a4[i].y * inva,
                e[4 * i + 2] * invd + a4[i].z * inva,
                e[4 * i + 3] * invd + a4[i].w * inva);
        }
    }
}

// ---------------------------------------------------------------------------
// Persistent attention v5.1 + fused output projection tail.
// Same as R14 but validity mask packed into ONE 16-bit register (was 16 fp32
// regs) -> frees ~15 registers, off the 128-reg cap.
// ---------------------------------------------------------------------------
#define SM_K   0
#define SM_V   (512 * 36)                   // K: 512 x 36
#define SM_PS  (SM_V + 512 * 40)            // V: 512 x 40 (conflict-free)
#define SM_GO  (SM_PS + 256)                // G stage (32 x 520) / Ored alias
#define GST    520
#define ORS    34
#define ATT_SMEM ((SM_GO + 32 * GST) * 4)   // 223232 B

__global__ void __launch_bounds__(512) attn_tc(
    const int* __restrict__ mask,
    const float* __restrict__ Wo, const float* __restrict__ bo,
    float* __restrict__ out)
{
    extern __shared__ unsigned smu[];
    const unsigned* Ks = smu + SM_K;
    const unsigned* Vs = smu + SM_V;
    float* psum = (float*)(smu + SM_PS);
    float* Gs = (float*)(smu + SM_GO);
    float* Ored = (float*)(smu + SM_GO);    // alias (disjoint in time)

    const int h = blockIdx.x, b = blockIdx.y;
    const int tid = threadIdx.x, warp = tid >> 5, lane = tid & 31;
    const int g = lane >> 2, tig = lane & 3;
    unsigned sb = (unsigned)__cvta_generic_to_shared(smu);

    const int wm = warp >> 3, wn = warp & 7;
    const unsigned* gQu = (const unsigned*)g_Q;

    // One-time cp.async: K (stride 36), V (stride 40), G tile 0 (stride 520)
#pragma unroll
    for (int i = 0; i < 8; i++) {
        int e = tid + 512 * i, r = e >> 3, c = e & 7;
        cpa16(sb + 4 * (SM_K + r * 36 + 4 * c),
              &g_K[((size_t)(b * NN + r)) * DD + h * DKK + 4 * c]);
        cpa16(sb + 4 * (SM_V + r * 40 + 4 * c),
              &g_V[((size_t)(b * NN + r)) * DD + h * DKK + 4 * c]);
    }
#pragma unroll
    for (int i = 0; i < 8; i++) {
        int e = tid + 512 * i, r = e >> 7, c4 = (e & 127) * 4;
        cpa16(sb + 4 * (SM_GO + r * GST + c4),
              &g_G[((size_t)(b * NN + r)) * NN + c4]);
    }
    CP_COMMIT();

    // Q fragments for tile 0 -> registers (LDG)
    unsigned qa[4][4];
    {
        size_t base0 = ((size_t)(b * NN + wm * 16 + g)) * DD + h * DKK;
        size_t base8 = base0 + 8 * DD;
#pragma unroll
        for (int k8 = 0; k8 < 4; k8++) {
            int k0 = k8 * 8;
            qa[k8][0] = gQu[base0 + k0 + tig];
            qa[k8][1] = gQu[base8 + k0 + tig];
            qa[k8][2] = gQu[base0 + k0 + tig + 4];
            qa[k8][3] = gQu[base8 + k0 + tig + 4];
        }
    }

    // validity mask -> ONE bitmask register (bit 2nt = col c, bit 2nt+1 = c+1)
    unsigned mbits = 0;
#pragma unroll
    for (int nt = 0; nt < 8; nt++) {
        int c = wn * 64 + nt * 8 + 2 * tig;
        if (mask[b * NN + c] != 0)     mbits |= (1u << (2 * nt));
        if (mask[b * NN + c + 1] != 0) mbits |= (1u << (2 * nt + 1));
    }
    CP_WAIT0();
    __syncthreads();

    const float EC = 0.17677669529663687f * 1.4426950408889634f;
    const int src0 = (lane & ~3) | (tig >> 1);
    const int src2 = (lane & ~3) | ((tig >> 1) + 2);
    const bool odd = (tig & 1) != 0;

    for (int qt = 0; qt < 16; qt++) {
        const int q0 = qt * 32;

        // --- P1: S = Q(regs) K^T; scores in registers
        float acc[8][4];
        {
#pragma unroll
            for (int nt = 0; nt < 8; nt++)
#pragma unroll
                for (int i = 0; i < 4; i++) acc[nt][i] = 0.f;
#pragma unroll
            for (int k8 = 0; k8 < 4; k8++) {
                int k0 = k8 * 8;
#pragma unroll
                for (int nt = 0; nt < 8; nt++) {
                    int key = wn * 64 + nt * 8;
                    unsigned b0 = Ks[(key + g) * 36 + k0 + tig];
                    unsigned b1 = Ks[(key + g) * 36 + k0 + tig + 4];
                    mma8(acc[nt], qa[k8][0], qa[k8][1], qa[k8][2], qa[k8][3], b0, b1);
                }
            }
        }

        // Prefetch Q fragments for tile qt+1 (registers)
        unsigned qn[4][4];
        if (qt < 15) {
            size_t base0 = ((size_t)(b * NN + q0 + 32 + wm * 16 + g)) * DD + h * DKK;
            size_t base8 = base0 + 8 * DD;
#pragma unroll
            for (int k8 = 0; k8 < 4; k8++) {
                int k0 = k8 * 8;
                qn[k8][0] = gQu[base0 + k0 + tig];
                qn[k8][1] = gQu[base8 + k0 + tig];
                qn[k8][2] = gQu[base0 + k0 + tig + 4];
                qn[k8][3] = gQu[base8 + k0 + tig + 4];
            }
        }

        // exp * validity (bitmask rematerialized); partial row sums -> psum
        float s0 = 0.f, s8 = 0.f;
#pragma unroll
        for (int nt = 0; nt < 8; nt++) {
            float m0 = (mbits & (1u << (2 * nt)))     ? 1.f : 0.f;
            float m1 = (mbits & (1u << (2 * nt + 1))) ? 1.f : 0.f;
            acc[nt][0] = ex2(acc[nt][0] * EC) * m0;
            acc[nt][1] = ex2(acc[nt][1] * EC) * m1;
            acc[nt][2] = ex2(acc[nt][2] * EC) * m0;
            acc[nt][3] = ex2(acc[nt][3] * EC) * m1;
            s0 += acc[nt][0] + acc[nt][1];
            s8 += acc[nt][2] + acc[nt][3];
        }
        s0 += __shfl_xor_sync(0xffffffffu, s0, 1);
        s0 += __shfl_xor_sync(0xffffffffu, s0, 2);
        s8 += __shfl_xor_sync(0xffffffffu, s8, 1);
        s8 += __shfl_xor_sync(0xffffffffu, s8, 2);
        if (tig == 0) {
            psum[(wm * 16 + g) * 8 + wn] = s0;
            psum[(wm * 16 + g + 8) * 8 + wn] = s8;
        }

        CP_WAIT0();        // G(qt) landed (only group in flight)
        __syncthreads();   // (1) psum + Gs(qt) visible

        // psum reduce + blend with Gs (conflict-free float2 LDS)
        {
            int r0 = wm * 16 + g, r8 = r0 + 8;
            float t0 = 0.f, t8 = 0.f;
#pragma unroll
            for (int i = 0; i < 8; i++) { t0 += psum[r0 * 8 + i]; t8 += psum[r8 * 8 + i]; }
            float inv0 = 0.3f / t0, inv8 = 0.3f / t8;
            const float* G0 = Gs + r0 * GST;
            const float* G8 = Gs + r8 * GST;
#pragma unroll
            for (int nt = 0; nt < 8; nt++) {
                int c = wn * 64 + nt * 8 + 2 * tig;
                float2 gv0 = *(const float2*)&G0[c];
                float2 gv8 = *(const float2*)&G8[c];
                acc[nt][0] = fmaf(acc[nt][0], inv0, gv0.x);
                acc[nt][1] = fmaf(acc[nt][1], inv0, gv0.y);
                acc[nt][2] = fmaf(acc[nt][2], inv8, gv8.x);
                acc[nt][3] = fmaf(acc[nt][3], inv8, gv8.y);
            }
        }
        __syncthreads();   // (B) all Gs reads done before Ored writes (alias)

        // --- P2: C->A shfl conversion, partial O over this warp's 64 keys
        {
            float accO[4][4];
#pragma unroll
            for (int nt2 = 0; nt2 < 4; nt2++)
#pragma unroll
                for (int i = 0; i < 4; i++) accO[nt2][i] = 0.f;

#pragma unroll
            for (int nt = 0; nt < 8; nt++) {
                float t00 = __shfl_sync(0xffffffffu, acc[nt][0], src0);
                float t01 = __shfl_sync(0xffffffffu, acc[nt][1], src0);
                float t20 = __shfl_sync(0xffffffffu, acc[nt][0], src2);
                float t21 = __shfl_sync(0xffffffffu, acc[nt][1], src2);
                float t10 = __shfl_sync(0xffffffffu, acc[nt][2], src0);
                float t11 = __shfl_sync(0xffffffffu, acc[nt][3], src0);
                float t30 = __shfl_sync(0xffffffffu, acc[nt][2], src2);
                float t31 = __shfl_sync(0xffffffffu, acc[nt][3], src2);
                unsigned a0 = f2tf(odd ? t01 : t00);
                unsigned a1 = f2tf(odd ? t11 : t10);
                unsigned a2 = f2tf(odd ? t21 : t20);
                unsigned a3 = f2tf(odd ? t31 : t30);
                int kv0 = wn * 64 + nt * 8;
#pragma unroll
                for (int nt2 = 0; nt2 < 4; nt2++) {
                    unsigned b0 = Vs[(kv0 + tig) * 40 + nt2 * 8 + g];
                    unsigned b1 = Vs[(kv0 + tig + 4) * 40 + nt2 * 8 + g];
                    mma8(accO[nt2], a0, a1, a2, a3, b0, b1);
                }
            }

            float* Or = Ored + wn * (32 * ORS);
            int r0 = wm * 16 + g;
#pragma unroll
            for (int nt2 = 0; nt2 < 4; nt2++) {
                int c = nt2 * 8 + 2 * tig;
                *(float2*)&Or[r0 * ORS + c] = make_float2(accO[nt2][0], accO[nt2][1]);
                *(float2*)&Or[(r0 + 8) * ORS + c] = make_float2(accO[nt2][2], accO[nt2][3]);
            }
        }
        __syncthreads();   // (2) Ored published

        // reduce 8 partials -> g_X (tf32 bits)
        {
            int row = tid >> 4, c2 = (tid & 15) << 1;
            float sx = 0.f, sy = 0.f;
#pragma unroll
            for (int w2 = 0; w2 < 8; w2++) {
                float2 v = *(const float2*)&Ored[w2 * (32 * ORS) + row * ORS + c2];
                sx += v.x; sy += v.y;
            }
            int grow = b * NN + q0 + row;
            int gcol = h * DKK + c2;
            *(float2*)&g_X[(size_t)grow * DD + gcol] =
                make_float2(__uint_as_float(f2tf(sx)), __uint_as_float(f2tf(sy)));
        }
        __syncthreads();   // (3) Ored reads done before next G fill overwrites

        // Issue G fill for next tile (overlaps next P1/exp)
        if (qt < 15) {
#pragma unroll
            for (int i = 0; i < 8; i++) {
                int e = tid + 512 * i, r = e >> 7, c4 = (e & 127) * 4;
                cpa16(sb + 4 * (SM_GO + r * GST + c4),
                      &g_G[((size_t)(b * NN + q0 + 32 + r)) * NN + c4]);
            }
            CP_COMMIT();
            // rotate Q fragment registers
#pragma unroll
            for (int k8 = 0; k8 < 4; k8++)
#pragma unroll
                for (int i = 0; i < 4; i++) qa[k8][i] = qn[k8][i];
        }
    }

    // ====================== fused output-projection tail ======================
    __threadfence();
    __syncthreads();
    if (tid == 0) {
        atomicAdd(&g_cnt[b], 1);
        while (atomicAdd(&g_cnt[b], 0) < HH) { }
    }
    __syncthreads();
    __threadfence();

    {
        const int m0 = b * NN + (h >> 1) * 128;
        const int n0 = (h & 1) * 128;
        const int twm = warp >> 2, twn = warp & 3;
        float* Xb = (float*)smu;             // K region
        float* Wb = (float*)(smu + SM_V);    // V region

#define TAIL_ISSUE(kt, buf)                                                    \
        do {                                                                   \
            _Pragma("unroll")                                                  \
            for (int i = 0; i < 2; i++) {                                      \
                int e = tid + 512 * i, r = e >> 3, c = e & 7;                  \
                cpa16(sb + 4 * ((buf) * 4608 + r * 36 + 4 * c),                \
                      &g_X[(size_t)(m0 + r) * DD + (kt) * 32 + 4 * c]);        \
                cpa16(sb + 4 * (SM_V + (buf) * 4608 + r * 36 + 4 * c),         \
                      &Wo[(size_t)(n0 + r) * DD + (kt) * 32 + 4 * c]);         \
            }                                                                  \
            CP_COMMIT();                                                       \
        } while (0)

        float acc[2][4][4];
#pragma unroll
        for (int mt = 0; mt < 2; mt++)
#pragma unroll
            for (int nt = 0; nt < 4; nt++)
#pragma unroll
                for (int i = 0; i < 4; i++) acc[mt][nt][i] = 0.f;

        TAIL_ISSUE(0, 0);
        for (int kt = 0; kt < 8; kt++) {
            CP_WAIT0();
            __syncthreads();
            if (kt < 7) TAIL_ISSUE(kt + 1, (kt + 1) & 1);

            const unsigned* xb = (const unsigned*)(Xb + (kt & 1) * 4608);
            const float* wb = Wb + (kt & 1) * 4608;

#pragma unroll
            for (int k8 = 0; k8 < 4; k8++) {
                int k0 = k8 * 8;
                unsigned a[2][4];
#pragma unroll
                for (int mt = 0; mt < 2; mt++) {
                    int r = twm * 32 + mt * 16;
                    a[mt][0] = xb[(r + g) * 36 + k0 + tig];
                    a[mt][1] = xb[(r + g + 8) * 36 + k0 + tig];
                    a[mt][2] = xb[(r + g) * 36 + k0 + tig + 4];
                    a[mt][3] = xb[(r + g + 8) * 36 + k0 + tig + 4];
                }
#pragma unroll
                for (int nt = 0; nt < 4; nt++) {
                    int cb = twn * 32 + nt * 8;
                    unsigned b0 = f2tf(wb[(cb + g) * 36 + k0 + tig]);
                    unsigned b1 = f2tf(wb[(cb + g) * 36 + k0 + tig + 4]);
                    mma8(acc[0][nt], a[0][0], a[0][1], a[0][2], a[0][3], b0, b1);
                    mma8(acc[1][nt], a[1][0], a[1][1], a[1][2], a[1][3], b0, b1);
                }
            }
        }

#pragma unroll
        for (int mt = 0; mt < 2; mt++) {
            int row = m0 + twm * 32 + mt * 16 + g;
#pragma unroll
            for (int nt = 0; nt < 4; nt++) {
                int col = n0 + twn * 32 + nt * 8 + 2 * tig;
                float b0 = bo[col], b1 = bo[col + 1];
                *(float2*)&out[(size_t)row * DD + col] =
                    make_float2(acc[mt][nt][0] + b0, acc[mt][nt][1] + b1);
                *(float2*)&out[(size_t)(row + 8) * DD + col] =
                    make_float2(acc[mt][nt][2] + b0, acc[mt][nt][3] + b1);
            }
        }
#undef TAIL_ISSUE
    }
}

// ---------------------------------------------------------------------------
// Launch: two kernels total.
// ---------------------------------------------------------------------------
extern "C" void kernel_launch(void* const* d_in, const int* in_sizes, int n_in,
                              void* d_out, int out_size)
{
    (void)in_sizes; (void)n_in; (void)out_size;
    const float* query = (const float*)d_in[0];
    const float* key_  = (const float*)d_in[1];
    const float* value = (const float*)d_in[2];
    const float* adj   = (const float*)d_in[3];
    const float* dist  = (const float*)d_in[4];
    const int*   mask  = (const int*)d_in[6];
    const float* Wq = (const float*)d_in[7],  *bq = (const float*)d_in[8];
    const float* Wk = (const float*)d_in[9],  *bk = (const float*)d_in[10];
    const float* Wv = (const float*)d_in[11], *bv = (const float*)d_in[12];
    const float* Wo = (const float*)d_in[13], *bo = (const float*)d_in[14];
    float* out = (float*)d_out;

    static int attr_done = 0;
    if (!attr_done) {
        cudaFuncSetAttribute(fused_qkv_g, cudaFuncAttributeMaxDynamicSharedMemorySize, GEMM_SMEM_BYTES);
        cudaFuncSetAttribute(attn_tc,     cudaFuncAttributeMaxDynamicSharedMemorySize, ATT_SMEM);
        attr_done = 1;
    }

    fused_qkv_g<<<dim3(BB * NN / 128, DD / 64, 4), 256, GEMM_SMEM_BYTES>>>(
        query, key_, value, Wq, bq, Wk, bk, Wv, bv, dist, adj, mask);

    attn_tc<<<dim3(HH, BB), 512, ATT_SMEM>>>(mask, Wo, bo, out);
}

// round 16
// speedup vs baseline: 1.0717x; 1.0686x over previous
#include <cuda_runtime.h>

#define BB 16
#define NN 512
#define DD 256
#define HH 8
#define DKK 32

// Scratch (device globals). g_Q/g_K/g_V/g_X hold tf32-rounded bit patterns.
__device__ __align__(128) float g_Q[BB * NN * DD];
__device__ __align__(128) float g_K[BB * NN * DD];
__device__ __align__(128) float g_V[BB * NN * DD];
__device__ __align__(128) float g_X[BB * NN * DD];
__device__ __align__(128) float g_G[BB * NN * NN];
__device__ int g_cnt[BB];   // per-batch arrival counters (zeroed each launch)

// ---------------------------------------------------------------------------
// helpers
// ---------------------------------------------------------------------------
__device__ __forceinline__ unsigned f2tf(float x) {
    unsigned r;
    asm("cvt.rna.tf32.f32 %0, %1;" : "=r"(r) : "f"(x));
    return r;
}

__device__ __forceinline__ float ex2(float x) {
    float y;
    asm("ex2.approx.ftz.f32 %0, %1;" : "=f"(y) : "f"(x));
    return y;
}

__device__ __forceinline__ void mma8(float* c,
                                     unsigned a0, unsigned a1, unsigned a2, unsigned a3,
                                     unsigned b0, unsigned b1) {
    asm volatile(
        "mma.sync.aligned.m16n8k8.row.col.f32.tf32.tf32.f32 "
        "{%0,%1,%2,%3},{%4,%5,%6,%7},{%8,%9},{%0,%1,%2,%3};"
        : "+f"(c[0]), "+f"(c[1]), "+f"(c[2]), "+f"(c[3])
        : "r"(a0), "r"(a1), "r"(a2), "r"(a3), "r"(b0), "r"(b1));
}

__device__ __forceinline__ void cpa16(unsigned saddr, const void* gptr) {
    asm volatile("cp.async.cg.shared.global [%0], [%1], 16;" :: "r"(saddr), "l"(gptr));
}
#define CP_COMMIT() asm volatile("cp.async.commit_group;")
#define CP_WAIT0()  asm volatile("cp.async.wait_group 0;")
#define CP_WAIT1()  asm volatile("cp.async.wait_group 1;")

// ---------------------------------------------------------------------------
// GEMM core v4b (identical to R13): Y = X @ W^T + bias; K=256. 256 thr.
// ---------------------------------------------------------------------------
#define GS_X 4608
#define GS_W 2304
#define GEMM_SMEM_BYTES ((2 * GS_X + 2 * GS_W) * 4)

__device__ __forceinline__ void gemm_issue4(
    unsigned sb, const float* __restrict__ X, const float* __restrict__ W,
    int m0, int n0, int kt, int tid)
{
    int buf = kt & 1;
#pragma unroll
    for (int i = 0; i < 4; i++) {
        int e = tid + 256 * i, r = e >> 3, c = e & 7;
        cpa16(sb + 4 * (buf * GS_X + r * 36 + 4 * c),
              &X[(size_t)(m0 + r) * DD + kt * 32 + 4 * c]);
    }
#pragma unroll
    for (int i = 0; i < 2; i++) {
        int e = tid + 256 * i, r = e >> 3, c = e & 7;
        cpa16(sb + 4 * (2 * GS_X + buf * GS_W + r * 36 + 4 * c),
              &W[(size_t)(n0 + r) * DD + kt * 32 + 4 * c]);
    }
    CP_COMMIT();
}

__device__ __forceinline__ void gemm_core4(
    const float* __restrict__ X, const float* __restrict__ W,
    const float* __restrict__ bias, float* __restrict__ Y,
    int cvt_a, int cvt_out, float* sm, int m0, int n0)
{
    const int tid = threadIdx.x;
    const int warp = tid >> 5, lane = tid & 31;
    const int g = lane >> 2, tig = lane & 3;
    const int wm = warp >> 1, wn = warp & 1;
    unsigned sb = (unsigned)__cvta_generic_to_shared(sm);

    float acc[2][4][4];
#pragma unroll
    for (int mt = 0; mt < 2; mt++)
#pragma unroll
        for (int nt = 0; nt < 4; nt++)
#pragma unroll
            for (int i = 0; i < 4; i++) acc[mt][nt][i] = 0.f;

    gemm_issue4(sb, X, W, m0, n0, 0, tid);

    for (int kt = 0; kt < 8; kt++) {
        CP_WAIT0();
        __syncthreads();
        if (kt < 7) gemm_issue4(sb, X, W, m0, n0, kt + 1, tid);

        const float* xb = sm + (kt & 1) * GS_X;
        const float* wb = sm + 2 * GS_X + (kt & 1) * GS_W;
        const unsigned* xbu = (const unsigned*)xb;

#pragma unroll
        for (int k8 = 0; k8 < 4; k8++) {
            int k0 = k8 * 8;
            unsigned a[2][4];
#pragma unroll
            for (int mt = 0; mt < 2; mt++) {
                int r = wm * 32 + mt * 16;
                if (cvt_a) {
                    a[mt][0] = f2tf(xb[(r + g) * 36 + k0 + tig]);
                    a[mt][1] = f2tf(xb[(r + g + 8) * 36 + k0 + tig]);
                    a[mt][2] = f2tf(xb[(r + g) * 36 + k0 + tig + 4]);
                    a[mt][3] = f2tf(xb[(r + g + 8) * 36 + k0 + tig + 4]);
                } else {
                    a[mt][0] = xbu[(r + g) * 36 + k0 + tig];
                    a[mt][1] = xbu[(r + g + 8) * 36 + k0 + tig];
                    a[mt][2] = xbu[(r + g) * 36 + k0 + tig + 4];
                    a[mt][3] = xbu[(r + g + 8) * 36 + k0 + tig + 4];
                }
            }
#pragma unroll
            for (int nt = 0; nt < 4; nt++) {
                int cb = wn * 32 + nt * 8;
                unsigned b0 = f2tf(wb[(cb + g) * 36 + k0 + tig]);
                unsigned b1 = f2tf(wb[(cb + g) * 36 + k0 + tig + 4]);
                mma8(acc[0][nt], a[0][0], a[0][1], a[0][2], a[0][3], b0, b1);
                mma8(acc[1][nt], a[1][0], a[1][1], a[1][2], a[1][3], b0, b1);
            }
        }
    }

#pragma unroll
    for (int mt = 0; mt < 2; mt++) {
        int row = m0 + wm * 32 + mt * 16 + g;
#pragma unroll
        for (int nt = 0; nt < 4; nt++) {
            int col = n0 + wn * 32 + nt * 8 + 2 * tig;
            float b0 = bias[col], b1 = bias[col + 1];
            float v00 = acc[mt][nt][0] + b0, v01 = acc[mt][nt][1] + b1;
            float v10 = acc[mt][nt][2] + b0, v11 = acc[mt][nt][3] + b1;
            if (cvt_out) {
                v00 = __uint_as_float(f2tf(v00)); v01 = __uint_as_float(f2tf(v01));
                v10 = __uint_as_float(f2tf(v10)); v11 = __uint_as_float(f2tf(v11));
            }
            *(float2*)&Y[(size_t)row * DD + col] = make_float2(v00, v01);
            *(float2*)&Y[(size_t)(row + 8) * DD + col] = make_float2(v10, v11);
        }
    }
}

// ---------------------------------------------------------------------------
// Fused launch 1 (identical to R13): z=0/1/2 -> Q/K/V projection;
// z=3 -> build_G (warp-per-row, no barriers) + counter zeroing.
// ---------------------------------------------------------------------------
__global__ void __launch_bounds__(256, 4) fused_qkv_g(
    const float* __restrict__ query, const float* __restrict__ key_,
    const float* __restrict__ value,
    const float* __restrict__ Wq, const float* __restrict__ bq,
    const float* __restrict__ Wk, const float* __restrict__ bk,
    const float* __restrict__ Wv, const float* __restrict__ bv,
    const float* __restrict__ dist, const float* __restrict__ adj,
    const int* __restrict__ mask)
{
    extern __shared__ float sm[];
    const int z = blockIdx.z;
    if (z < 3) {
        const float* X = (z == 0) ? query : (z == 1) ? key_ : value;
        const float* W = (z == 0) ? Wq : (z == 1) ? Wk : Wv;
        const float* bias = (z == 0) ? bq : (z == 1) ? bk : bv;
        float* Y = (z == 0) ? g_Q : (z == 1) ? g_K : g_V;
        gemm_core4(X, W, bias, Y, 1, 1, sm, blockIdx.x * 128, blockIdx.y * 64);
        return;
    }

    const int id = blockIdx.y * 64 + blockIdx.x;   // 0..255
    if (id == 0 && threadIdx.x < BB) g_cnt[threadIdx.x] = 0;

    const int bb = id >> 4;
    const int r0 = (id & 15) * 32;
    const int warp = threadIdx.x >> 5, lane = threadIdx.x & 31;

    float v[16];
#pragma unroll
    for (int i = 0; i < 4; i++) {
        int4 mv = *(const int4*)&mask[bb * NN + 4 * lane + 128 * i];
        v[4 * i + 0] = mv.x ? 1.f : 0.f;
        v[4 * i + 1] = mv.y ? 1.f : 0.f;
        v[4 * i + 2] = mv.z ? 1.f : 0.f;
        v[4 * i + 3] = mv.w ? 1.f : 0.f;
    }

    for (int rr = 0; rr < 4; rr++) {
        int row = r0 + warp * 4 + rr;
        size_t rb = ((size_t)bb * NN + row) * NN;

        float4 d4[4], a4[4];
#pragma unroll
        for (int i = 0; i < 4; i++) {
            d4[i] = *(const float4*)&dist[rb + 4 * lane + 128 * i];
            a4[i] = *(const float4*)&adj[rb + 4 * lane + 128 * i];
        }
        float e[16];
        float se = 0.f, sa = 0.f;
#pragma unroll
        for (int i = 0; i < 4; i++) {
            e[4 * i + 0] = v[4 * i + 0] * __expf(-d4[i].x);
            e[4 * i + 1] = v[4 * i + 1] * __expf(-d4[i].y);
            e[4 * i + 2] = v[4 * i + 2] * __expf(-d4[i].z);
            e[4 * i + 3] = v[4 * i + 3] * __expf(-d4[i].w);
            se += (e[4 * i] + e[4 * i + 1]) + (e[4 * i + 2] + e[4 * i + 3]);
            sa += (a4[i].x + a4[i].y) + (a4[i].z + a4[i].w);
        }
#pragma unroll
        for (int o = 16; o > 0; o >>= 1) {
            se += __shfl_xor_sync(0xffffffffu, se, o);
            sa += __shfl_xor_sync(0xffffffffu, sa, o);
        }
        float invd = 0.3f / se;
        float inva = 0.4f / (sa + 1e-6f);
#pragma unroll
        for (int i = 0; i < 4; i++) {
            *(float4*)&g_G[rb + 4 * lane + 128 * i] = make_float4(
                e[4 * i + 0] * invd + a4[i].x * inva,
                e[4 * i + 1] * invd + a4[i].y * inva,
                e[4 * i + 2] * invd + a4[i].z * inva,
                e[4 * i + 3] * invd + a4[i].w * inva);
        }
    }
}

// ---------------------------------------------------------------------------
// Persistent attention v4.1 (R13 + V stride 40) + fused output projection.
// Q staged in smem double-buffer (as R13; keeps regs ~84). V at stride 40 ->
// conflict-free B-fragment loads. G staged per tile (stride 520), aliasing
// the Ored exchange buffer. smem = 232448 B (227 KB max).
// ---------------------------------------------------------------------------
#define SM_K   0
#define SM_V   (512 * 36)                   // K: 512 x 36
#define SM_QB  (SM_V + 512 * 40)            // V: 512 x 40 (conflict-free)
#define SM_PS  (SM_QB + 2 * 32 * 36)        // Q: 2 x 32 x 36
#define SM_GO  (SM_PS + 256)                // G stage (32 x 520) / Ored alias
#define GST    520
#define ORS    34
#define ATT_SMEM ((SM_GO + 32 * GST) * 4)   // 232448 B = 227 KB

__global__ void __launch_bounds__(512) attn_tc(
    const int* __restrict__ mask,
    const float* __restrict__ Wo, const float* __restrict__ bo,
    float* __restrict__ out)
{
    extern __shared__ unsigned smu[];
    const unsigned* Ks = smu + SM_K;
    const unsigned* Vs = smu + SM_V;
    float* psum = (float*)(smu + SM_PS);
    float* Gs = (float*)(smu + SM_GO);
    float* Ored = (float*)(smu + SM_GO);    // alias (disjoint in time)

    const int h = blockIdx.x, b = blockIdx.y;
    const int tid = threadIdx.x, warp = tid >> 5, lane = tid & 31;
    const int g = lane >> 2, tig = lane & 3;
    unsigned sb = (unsigned)__cvta_generic_to_shared(smu);

    const int wm = warp >> 3, wn = warp & 7;

    // One-time cp.async: K (36), V (40), Q tile 0 (36), G tile 0 (520)
#pragma unroll
    for (int i = 0; i < 8; i++) {
        int e = tid + 512 * i, r = e >> 3, c = e & 7;
        cpa16(sb + 4 * (SM_K + r * 36 + 4 * c),
              &g_K[((size_t)(b * NN + r)) * DD + h * DKK + 4 * c]);
        cpa16(sb + 4 * (SM_V + r * 40 + 4 * c),
              &g_V[((size_t)(b * NN + r)) * DD + h * DKK + 4 * c]);
    }
    if (tid < 256) {
        int r = tid >> 3, c = tid & 7;
        cpa16(sb + 4 * (SM_QB + r * 36 + 4 * c),
              &g_Q[((size_t)(b * NN + r)) * DD + h * DKK + 4 * c]);
    }
#pragma unroll
    for (int i = 0; i < 8; i++) {
        int e = tid + 512 * i, r = e >> 7, c4 = (e & 127) * 4;
        cpa16(sb + 4 * (SM_GO + r * GST + c4),
              &g_G[((size_t)(b * NN + r)) * NN + c4]);
    }
    CP_COMMIT();

    // validity mask -> registers (tile-invariant per warp/lane)
    float v0[8], v1[8];
#pragma unroll
    for (int nt = 0; nt < 8; nt++) {
        int c = wn * 64 + nt * 8 + 2 * tig;
        v0[nt] = (mask[b * NN + c] != 0) ? 1.f : 0.f;
        v1[nt] = (mask[b * NN + c + 1] != 0) ? 1.f : 0.f;
    }
    CP_WAIT0();
    __syncthreads();

    const float EC = 0.17677669529663687f * 1.4426950408889634f;
    const int src0 = (lane & ~3) | (tig >> 1);
    const int src2 = (lane & ~3) | ((tig >> 1) + 2);
    const bool odd = (tig & 1) != 0;

    for (int qt = 0; qt < 16; qt++) {
        const int q0 = qt * 32;
        const unsigned* Qb = smu + SM_QB + (qt & 1) * (32 * 36);

        // --- P1: S = Q K^T; scores in registers
        float acc[8][4];
        {
            unsigned a[4][4];
#pragma unroll
            for (int k8 = 0; k8 < 4; k8++) {
                int k0 = k8 * 8, r = wm * 16;
                a[k8][0] = Qb[(r + g) * 36 + k0 + tig];
                a[k8][1] = Qb[(r + g + 8) * 36 + k0 + tig];
                a[k8][2] = Qb[(r + g) * 36 + k0 + tig + 4];
                a[k8][3] = Qb[(r + g + 8) * 36 + k0 + tig + 4];
            }
#pragma unroll
            for (int nt = 0; nt < 8; nt++)
#pragma unroll
                for (int i = 0; i < 4; i++) acc[nt][i] = 0.f;
#pragma unroll
            for (int k8 = 0; k8 < 4; k8++) {
                int k0 = k8 * 8;
#pragma unroll
                for (int nt = 0; nt < 8; nt++) {
                    int key = wn * 64 + nt * 8;
                    unsigned b0 = Ks[(key + g) * 36 + k0 + tig];
                    unsigned b1 = Ks[(key + g) * 36 + k0 + tig + 4];
                    mma8(acc[nt], a[k8][0], a[k8][1], a[k8][2], a[k8][3], b0, b1);
                }
            }
        }

        // exp * validity (regs); partial row sums -> psum
        float s0 = 0.f, s8 = 0.f;
#pragma unroll
        for (int nt = 0; nt < 8; nt++) {
            acc[nt][0] = ex2(acc[nt][0] * EC) * v0[nt];
            acc[nt][1] = ex2(acc[nt][1] * EC) * v1[nt];
            acc[nt][2] = ex2(acc[nt][2] * EC) * v0[nt];
            acc[nt][3] = ex2(acc[nt][3] * EC) * v1[nt];
            s0 += acc[nt][0] + acc[nt][1];
            s8 += acc[nt][2] + acc[nt][3];
        }
        s0 += __shfl_xor_sync(0xffffffffu, s0, 1);
        s0 += __shfl_xor_sync(0xffffffffu, s0, 2);
        s8 += __shfl_xor_sync(0xffffffffu, s8, 1);
        s8 += __shfl_xor_sync(0xffffffffu, s8, 2);
        if (tig == 0) {
            psum[(wm * 16 + g) * 8 + wn] = s0;
            psum[(wm * 16 + g + 8) * 8 + wn] = s8;
        }

        // Q prefetch (buffer last read at qt-1) then wait for G(qt)
        if (qt < 15) {
            if (tid < 256) {
                int r = tid >> 3, c = tid & 7;
                cpa16(sb + 4 * (SM_QB + ((qt + 1) & 1) * (32 * 36) + r * 36 + 4 * c),
                      &g_Q[((size_t)(b * NN + q0 + 32 + r)) * DD + h * DKK + 4 * c]);
            }
            CP_COMMIT();
            CP_WAIT1();   // G(qt) landed; Q prefetch may remain in flight
        } else {
            CP_WAIT0();
        }
        __syncthreads();   // (1) psum + Gs(qt) visible

        // psum reduce + blend with Gs (conflict-free float2 LDS)
        {
            int r0 = wm * 16 + g, r8 = r0 + 8;
            float t0 = 0.f, t8 = 0.f;
#pragma unroll
            for (int i = 0; i < 8; i++) { t0 += psum[r0 * 8 + i]; t8 += psum[r8 * 8 + i]; }
            float inv0 = 0.3f / t0, inv8 = 0.3f / t8;
            const float* G0 = Gs + r0 * GST;
            const float* G8 = Gs + r8 * GST;
#pragma unroll
            for (int nt = 0; nt < 8; nt++) {
                int c = wn * 64 + nt * 8 + 2 * tig;
                float2 gv0 = *(const float2*)&G0[c];
                float2 gv8 = *(const float2*)&G8[c];
                acc[nt][0] = fmaf(acc[nt][0], inv0, gv0.x);
                acc[nt][1] = fmaf(acc[nt][1], inv0, gv0.y);
                acc[nt][2] = fmaf(acc[nt][2], inv8, gv8.x);
                acc[nt][3] = fmaf(acc[nt][3], inv8, gv8.y);
            }
        }
        __syncthreads();   // (B) all Gs reads done before Ored writes (alias)

        // --- P2: C->A shfl conversion, partial O over this warp's 64 keys
        {
            float accO[4][4];
#pragma unroll
            for (int nt2 = 0; nt2 < 4; nt2++)
#pragma unroll
                for (int i = 0; i < 4; i++) accO[nt2][i] = 0.f;

#pragma unroll
            for (int nt = 0; nt < 8; nt++) {
                float t00 = __shfl_sync(0xffffffffu, acc[nt][0], src0);
                float t01 = __shfl_sync(0xffffffffu, acc[nt][1], src0);
                float t20 = __shfl_sync(0xffffffffu, acc[nt][0], src2);
                float t21 = __shfl_sync(0xffffffffu, acc[nt][1], src2);
                float t10 = __shfl_sync(0xffffffffu, acc[nt][2], src0);
                float t11 = __shfl_sync(0xffffffffu, acc[nt][3], src0);
                float t30 = __shfl_sync(0xffffffffu, acc[nt][2], src2);
                float t31 = __shfl_sync(0xffffffffu, acc[nt][3], src2);
                unsigned a0 = f2tf(odd ? t01 : t00);
                unsigned a1 = f2tf(odd ? t11 : t10);
                unsigned a2 = f2tf(odd ? t21 : t20);
                unsigned a3 = f2tf(odd ? t31 : t30);
                int kv0 = wn * 64 + nt * 8;
#pragma unroll
                for (int nt2 = 0; nt2 < 4; nt2++) {
                    unsigned b0 = Vs[(kv0 + tig) * 40 + nt2 * 8 + g];
                    unsigned b1 = Vs[(kv0 + tig + 4) * 40 + nt2 * 8 + g];
                    mma8(accO[nt2], a0, a1, a2, a3, b0, b1);
                }
            }

            float* Or = Ored + wn * (32 * ORS);
            int r0 = wm * 16 + g;
#pragma unroll
            for (int nt2 = 0; nt2 < 4; nt2++) {
                int c = nt2 * 8 + 2 * tig;
                *(float2*)&Or[r0 * ORS + c] = make_float2(accO[nt2][0], accO[nt2][1]);
                *(float2*)&Or[(r0 + 8) * ORS + c] = make_float2(accO[nt2][2], accO[nt2][3]);
            }
        }
        CP_WAIT0();        // Q prefetch landed (no-op at qt=15)
        __syncthreads();   // (2) Ored + Qb published

        // reduce 8 partials -> g_X (tf32 bits)
        {
            int row = tid >> 4, c2 = (tid & 15) << 1;
            float sx = 0.f, sy = 0.f;
#pragma unroll
            for (int w2 = 0; w2 < 8; w2++) {
                float2 v = *(const float2*)&Ored[w2 * (32 * ORS) + row * ORS + c2];
                sx += v.x; sy += v.y;
            }
            int grow = b * NN + q0 + row;
            int gcol = h * DKK + c2;
            *(float2*)&g_X[(size_t)grow * DD + gcol] =
                make_float2(__uint_as_float(f2tf(sx)), __uint_as_float(f2tf(sy)));
        }
        __syncthreads();   // (3) Ored reads done before next G fill overwrites

        // Issue G fill for next tile (overlaps next P1/exp)
        if (qt < 15) {
#pragma unroll
            for (int i = 0; i < 8; i++) {
                int e = tid + 512 * i, r = e >> 7, c4 = (e & 127) * 4;
                cpa16(sb + 4 * (SM_GO + r * GST + c4),
                      &g_G[((size_t)(b * NN + q0 + 32 + r)) * NN + c4]);
            }
            CP_COMMIT();
        }
    }

    // ====================== fused output-projection tail ======================
    __threadfence();
    __syncthreads();
    if (tid == 0) {
        atomicAdd(&g_cnt[b], 1);
        while (atomicAdd(&g_cnt[b], 0) < HH) { }
    }
    __syncthreads();
    __threadfence();

    {
        const int m0 = b * NN + (h >> 1) * 128;
        const int n0 = (h & 1) * 128;
        const int twm = warp >> 2, twn = warp & 3;
        float* Xb = (float*)smu;             // K region
        float* Wb = (float*)(smu + SM_V);    // V region

#define TAIL_ISSUE(kt, buf)                                                    \
        do {                                                                   \
            _Pragma("unroll")                                                  \
            for (int i = 0; i < 2; i++) {                                      \
                int e = tid + 512 * i, r = e >> 3, c = e & 7;                  \
                cpa16(sb + 4 * ((buf) * 4608 + r * 36 + 4 * c),                \
                      &g_X[(size_t)(m0 + r) * DD + (kt) * 32 + 4 * c]);        \
                cpa16(sb + 4 * (SM_V + (buf) * 4608 + r * 36 + 4 * c),         \
                      &Wo[(size_t)(n0 + r) * DD + (kt) * 32 + 4 * c]);         \
            }                                                                  \
            CP_COMMIT();                                                       \
        } while (0)

        float acc[2][4][4];
#pragma unroll
        for (int mt = 0; mt < 2; mt++)
#pragma unroll
            for (int nt = 0; nt < 4; nt++)
#pragma unroll
                for (int i = 0; i < 4; i++) acc[mt][nt][i] = 0.f;

        TAIL_ISSUE(0, 0);
        for (int kt = 0; kt < 8; kt++) {
            CP_WAIT0();
            __syncthreads();
            if (kt < 7) TAIL_ISSUE(kt + 1, (kt + 1) & 1);

            const unsigned* xb = (const unsigned*)(Xb + (kt & 1) * 4608);
            const float* wb = Wb + (kt & 1) * 4608;

#pragma unroll
            for (int k8 = 0; k8 < 4; k8++) {
                int k0 = k8 * 8;
                unsigned a[2][4];
#pragma unroll
                for (int mt = 0; mt < 2; mt++) {
                    int r = twm * 32 + mt * 16;
                    a[mt][0] = xb[(r + g) * 36 + k0 + tig];
                    a[mt][1] = xb[(r + g + 8) * 36 + k0 + tig];
                    a[mt][2] = xb[(r + g) * 36 + k0 + tig + 4];
                    a[mt][3] = xb[(r + g + 8) * 36 + k0 + tig + 4];
                }
#pragma unroll
                for (int nt = 0; nt < 4; nt++) {
                    int cb = twn * 32 + nt * 8;
                    unsigned b0 = f2tf(wb[(cb + g) * 36 + k0 + tig]);
                    unsigned b1 = f2tf(wb[(cb + g) * 36 + k0 + tig + 4]);
                    mma8(acc[0][nt], a[0][0], a[0][1], a[0][2], a[0][3], b0, b1);
                    mma8(acc[1][nt], a[1][0], a[1][1], a[1][2], a[1][3], b0, b1);
                }
            }
        }

#pragma unroll
        for (int mt = 0; mt < 2; mt++) {
            int row = m0 + twm * 32 + mt * 16 + g;
#pragma unroll
            for (int nt = 0; nt < 4; nt++) {
                int col = n0 + twn * 32 + nt * 8 + 2 * tig;
                float b0 = bo[col], b1 = bo[col + 1];
                *(float2*)&out[(size_t)row * DD + col] =
                    make_float2(acc[mt][nt][0] + b0, acc[mt][nt][1] + b1);
                *(float2*)&out[(size_t)(row + 8) * DD + col] =
                    make_float2(acc[mt][nt][2] + b0, acc[mt][nt][3] + b1);
            }
        }
#undef TAIL_ISSUE
    }
}

// ---------------------------------------------------------------------------
// Launch: two kernels total.
// ---------------------------------------------------------------------------
extern "C" void kernel_launch(void* const* d_in, const int* in_sizes, int n_in,
                              void* d_out, int out_size)
{
    (void)in_sizes; (void)n_in; (void)out_size;
    const float* query = (const float*)d_in[0];
    const float* key_  = (const float*)d_in[1];
    const float* value = (const float*)d_in[2];
    const float* adj   = (const float*)d_in[3];
    const float* dist  = (const float*)d_in[4];
    const int*   mask  = (const int*)d_in[6];
    const float* Wq = (const float*)d_in[7],  *bq = (const float*)d_in[8];
    const float* Wk = (const float*)d_in[9],  *bk = (const float*)d_in[10];
    const float* Wv = (const float*)d_in[11], *bv = (const float*)d_in[12];
    const float* Wo = (const float*)d_in[13], *bo = (const float*)d_in[14];
    float* out = (float*)d_out;

    static int attr_done = 0;
    if (!attr_done) {
        cudaFuncSetAttribute(fused_qkv_g, cudaFuncAttributeMaxDynamicSharedMemorySize, GEMM_SMEM_BYTES);
        cudaFuncSetAttribute(attn_tc,     cudaFuncAttributeMaxDynamicSharedMemorySize, ATT_SMEM);
        attr_done = 1;
    }

    fused_qkv_g<<<dim3(BB * NN / 128, DD / 64, 4), 256, GEMM_SMEM_BYTES>>>(
        query, key_, value, Wq, bq, Wk, bk, Wv, bv, dist, adj, mask);

    attn_tc<<<dim3(HH, BB), 512, ATT_SMEM>>>(mask, Wo, bo, out);
}